// round 12
// baseline (speedup 1.0000x reference)
#include <cuda_runtime.h>
#include <float.h>

// Shapes (fixed): network_mesh (4,3,32,32) f32 = d_in[0]; pc (4,3,4096) f32 = d_in[1].
// Output: scalar f32 = mean over 4*4096 nearest-refined-mesh squared distances.
#define B_       4
#define H_       32
#define W_       32
#define FAC_     3
#define OH_      94          // (32-1)*3+1
#define OW_      94
#define NMESH_   (OH_ * OW_) // 8836
#define M_       4096
#define SLICES_  37          // grid = 4*4*37 = 592 = exactly one wave at 4 CTAs/SM
#define SLICE_   240         // EVEN; 36*240=8640, last slice = 196 (even)
#define PAIRS_   (SLICE_ / 2)
#define THREADS_ 256
#define RPT_     4           // pc POINTS per thread
#define CHUNKS_  4           // 4096 / (256 thr * 4 pts)
#define NCOLS_   (B_ * CHUNKS_)   // 16 (b,chunk) columns, 37 CTAs each
#define SCALE_   4294967296.0     // 2^32 fixed-point scale for deterministic sum

// Allocation-free scratch. All of it is re-armed to its zero-state by the
// consuming CTA, so every graph replay starts from identical state.
__device__ unsigned int       g_best[B_ * M_];      // ~enc(min dist); 0 == +inf
__device__ unsigned int       g_colticket[NCOLS_];  // per-column CTA counters
__device__ unsigned long long g_isum;               // fixed-point total (int = deterministic)
__device__ unsigned int       g_fticket;            // column-finisher counter

union df2 { unsigned long long u; float2 f; };

__device__ __forceinline__ unsigned long long pack2(float lo, float hi) {
    df2 t; t.f = make_float2(lo, hi); return t.u;
}

// Packed dual-FMA (Blackwell f32x2 path). No packed f32 min exists in PTX.
__device__ __forceinline__ unsigned long long fma2(unsigned long long a,
                                                   unsigned long long b,
                                                   unsigned long long c) {
    unsigned long long r;
    asm("fma.rn.f32x2 %0, %1, %2, %3;" : "=l"(r) : "l"(a), "l"(b), "l"(c));
    return r;
}

// Monotonic float->uint key: larger float <=> larger key (handles negatives).
__device__ __forceinline__ unsigned int enc_f32(float f) {
    unsigned int u = __float_as_uint(f);
    return u ^ ((u >> 31) ? 0xFFFFFFFFu : 0x80000000u);
}
__device__ __forceinline__ float dec_f32(unsigned int e) {
    unsigned int u = (e & 0x80000000u) ? (e ^ 0x80000000u) : ~e;
    return __uint_as_float(u);
}

// ---------------------------------------------------------------------------
// Single kernel: fused refine + nearest-point minima (atomicMax of ~enc) +
// in-kernel deterministic reduction via non-blocking tickets.
// grid = (4,4,37) = 592 blocks: one co-resident wave at 4 CTAs/SM.
// ---------------------------------------------------------------------------
__global__ __launch_bounds__(THREADS_, 4)
void dist_kernel(const float* __restrict__ mesh, const float* __restrict__ pc,
                 float* __restrict__ out) {
    __shared__ ulonglong2 sa[PAIRS_];   // {x0,x1},{y0,y1}
    __shared__ ulonglong2 sb[PAIRS_];   // {z0,z1},{w0,w1}   w = |m|^2
    __shared__ long long  sred[THREADS_];
    __shared__ unsigned int s_t, s_f;

    const int b     = blockIdx.x;
    const int chunk = blockIdx.y;
    const int s     = blockIdx.z;

    const int base = s * SLICE_;
    const int cnt  = (base + SLICE_ <= NMESH_) ? SLICE_ : (NMESH_ - base);  // even

    // --- Inline bilinear refine (align_corners, factor 3) for this slice ---
    const float* __restrict__ m0 = mesh + (b * 3 + 0) * H_ * W_;
    const float* __restrict__ m1 = mesh + (b * 3 + 1) * H_ * W_;
    const float* __restrict__ m2 = mesh + (b * 3 + 2) * H_ * W_;

    if (threadIdx.x < cnt) {
        int i = threadIdx.x;                 // SLICE_ <= THREADS_, one pass
        int idx = base + i;
        int r = idx / OW_;
        int c = idx - r * OW_;
        int y0 = r / FAC_; if (y0 > H_ - 2) y0 = H_ - 2;
        int x0 = c / FAC_; if (x0 > W_ - 2) x0 = W_ - 2;
        float wy = (float)r / (float)FAC_ - (float)y0;
        float wx = (float)c / (float)FAC_ - (float)x0;
        int o00 = y0 * W_ + x0, o01 = o00 + 1, o10 = o00 + W_, o11 = o10 + 1;

        float t0 = m0[o00] * (1.0f - wx) + m0[o01] * wx;
        float u0 = m0[o10] * (1.0f - wx) + m0[o11] * wx;
        float v0 = t0 * (1.0f - wy) + u0 * wy;

        float t1 = m1[o00] * (1.0f - wx) + m1[o01] * wx;
        float u1 = m1[o10] * (1.0f - wx) + m1[o11] * wx;
        float v1 = t1 * (1.0f - wy) + u1 * wy;

        float t2 = m2[o00] * (1.0f - wx) + m2[o01] * wx;
        float u2 = m2[o10] * (1.0f - wx) + m2[o11] * wx;
        float v2 = t2 * (1.0f - wy) + u2 * wy;

        float w = fmaf(v0, v0, fmaf(v1, v1, v2 * v2));

        int jp   = i >> 1;
        int lane = i & 1;
        float* fa = (float*)sa;
        float* fb = (float*)sb;
        fa[4 * jp + lane]     = v0;
        fa[4 * jp + 2 + lane] = v1;
        fb[4 * jp + lane]     = v2;
        fb[4 * jp + 2 + lane] = w;
    }
    __syncthreads();

    // --- Load this thread's pc points; duplicate coords into packed regs ---
    const float* __restrict__ px = pc + (b * 3 + 0) * M_;
    const float* __restrict__ py = pc + (b * 3 + 1) * M_;
    const float* __restrict__ pz = pc + (b * 3 + 2) * M_;

    const int q0 = chunk * (THREADS_ * RPT_) + threadIdx.x;   // pc point index

    unsigned long long ax2[RPT_], ay2[RPT_], az2[RPT_];
    float b0[RPT_], b1[RPT_];
#pragma unroll
    for (int r = 0; r < RPT_; r++) {
        int q = q0 + r * THREADS_;
        float x = px[q], y = py[q], z = pz[q];
        ax2[r] = pack2(-2.0f * x, -2.0f * x);
        ay2[r] = pack2(-2.0f * y, -2.0f * y);
        az2[r] = pack2(-2.0f * z, -2.0f * z);
        b0[r] = FLT_MAX;
        b1[r] = FLT_MAX;
    }

    // --- Hot loop over mesh PAIRS: one packed FMA chain = 2 mesh distances ---
    const int pairs = cnt >> 1;
#pragma unroll 2
    for (int jp = 0; jp < pairs; jp++) {
        ulonglong2 A  = sa[jp];   // broadcast LDS.128: {x0,x1},{y0,y1}
        ulonglong2 Bv = sb[jp];   // {z0,z1},{w0,w1}
#pragma unroll
        for (int r = 0; r < RPT_; r++) {
            df2 t;
            t.u = fma2(A.x, ax2[r], fma2(A.y, ay2[r], fma2(Bv.x, az2[r], Bv.y)));
            b0[r] = fminf(b0[r], t.f.x);
            b1[r] = fminf(b1[r], t.f.y);
        }
    }

    // --- Epilogue: per-point order-independent atomic min (exact) ---
#pragma unroll
    for (int r = 0; r < RPT_; r++) {
        int q = q0 + r * THREADS_;
        float x = px[q], y = py[q], z = pz[q];
        float pp = fmaf(x, x, fmaf(y, y, z * z));
        float d  = fminf(b0[r], b1[r]) + pp;
        atomicMax(&g_best[b * M_ + q], ~enc_f32(d));   // 0 == +inf sentinel
    }

    // --- Column ticket: last of the 37 CTAs in this (b,chunk) column
    //     finalizes its 1024 points into the deterministic integer sum. ---
    __threadfence();
    if (threadIdx.x == 0)
        s_t = atomicAdd(&g_colticket[b * CHUNKS_ + chunk], 1u);
    __syncthreads();

    if (s_t == SLICES_ - 1) {
        __threadfence();                       // acquire writers' g_best stores
        if (threadIdx.x == 0)
            g_colticket[b * CHUNKS_ + chunk] = 0u;   // re-arm (no one else reads it)

        long long acc = 0;
#pragma unroll
        for (int r = 0; r < RPT_; r++) {
            int gi = b * M_ + q0 + r * THREADS_;
            float d = dec_f32(~g_best[gi]);
            g_best[gi] = 0u;                   // re-arm for next replay
            acc += __double2ll_rn((double)d * SCALE_);
        }
        sred[threadIdx.x] = acc;
        __syncthreads();
#pragma unroll
        for (int off = THREADS_ / 2; off > 0; off >>= 1) {
            if (threadIdx.x < off) sred[threadIdx.x] += sred[threadIdx.x + off];
            __syncthreads();
        }
        if (threadIdx.x == 0) {
            atomicAdd(&g_isum, (unsigned long long)sred[0]);  // int add = deterministic
            __threadfence();
            s_f = atomicAdd(&g_fticket, 1u);
        }
        __syncthreads();

        // --- Final ticket: last column-finisher emits the mean + resets ---
        if (s_f == NCOLS_ - 1 && threadIdx.x == 0) {
            __threadfence();
            long long tot = (long long)g_isum;
            out[0] = (float)((double)tot / SCALE_ / (double)(B_ * M_));
            g_isum = 0ull;                     // re-arm for next replay
            g_fticket = 0u;
        }
    }
}

// ---------------------------------------------------------------------------
extern "C" void kernel_launch(void* const* d_in, const int* in_sizes, int n_in,
                              void* d_out, int out_size) {
    const float* mesh = (const float*)d_in[0];
    const float* pc   = (const float*)d_in[1];
    float* out = (float*)d_out;

    dim3 grid(B_, CHUNKS_, SLICES_);
    dist_kernel<<<grid, THREADS_>>>(mesh, pc, out);
}

// round 13
// speedup vs baseline: 1.0648x; 1.0648x over previous
#include <cuda_runtime.h>
#include <float.h>

// Shapes (fixed): network_mesh (4,3,32,32) f32 = d_in[0]; pc (4,3,4096) f32 = d_in[1].
// Output: scalar f32 = mean over 4*4096 nearest-refined-mesh squared distances.
#define B_       4
#define H_       32
#define W_       32
#define FAC_     3
#define OH_      94          // (32-1)*3+1
#define OW_      94
#define NMESH_   (OH_ * OW_) // 8836
#define M_       4096
#define SLICES_  37          // grid = 4*4*37 = 592 = exactly one wave at 4 CTAs/SM
#define SLICE_   240         // EVEN; 36*240=8640, last slice = 196 (even)
#define PAIRS_   (SLICE_ / 2)
#define THREADS_ 256
#define RPT_     4           // pc POINTS per thread
#define CHUNKS_  4           // 4096 / (256 thr * 4 pts)
#define NCOLS_   (B_ * CHUNKS_)   // 16 (b,chunk) columns, 37 CTAs each
#define SCALEF_  4294967296.0f    // 2^32 fixed-point scale (float mul = deterministic)
#define SCALED_  4294967296.0     // for the final (host-side-equivalent) divide

// Allocation-free scratch. Every word is re-armed to its zero-state by the
// consuming CTA, so each graph replay starts from identical state.
__device__ unsigned int       g_best[B_ * M_];      // ~enc(min dist); 0 == +inf
__device__ unsigned int       g_colticket[NCOLS_];  // per-column CTA counters
__device__ unsigned long long g_isum;               // fixed-point total (int = deterministic)
__device__ unsigned int       g_fticket;            // column-finisher counter

union df2 { unsigned long long u; float2 f; };

__device__ __forceinline__ unsigned long long pack2(float lo, float hi) {
    df2 t; t.f = make_float2(lo, hi); return t.u;
}

// Packed dual-FMA (Blackwell f32x2 path). No packed f32 min exists in PTX.
__device__ __forceinline__ unsigned long long fma2(unsigned long long a,
                                                   unsigned long long b,
                                                   unsigned long long c) {
    unsigned long long r;
    asm("fma.rn.f32x2 %0, %1, %2, %3;" : "=l"(r) : "l"(a), "l"(b), "l"(c));
    return r;
}

// Monotonic float->uint key: larger float <=> larger key (handles negatives).
__device__ __forceinline__ unsigned int enc_f32(float f) {
    unsigned int u = __float_as_uint(f);
    return u ^ ((u >> 31) ? 0xFFFFFFFFu : 0x80000000u);
}
__device__ __forceinline__ float dec_f32(unsigned int e) {
    unsigned int u = (e & 0x80000000u) ? (e ^ 0x80000000u) : ~e;
    return __uint_as_float(u);
}

// ---------------------------------------------------------------------------
// Quarantined finalization: runs in ONE CTA per (b,chunk) column (the last to
// finish). __noinline__ keeps its register demand from contaminating the hot
// loop's allocation/schedule. Integer fixed-point => deterministic across
// replays regardless of CTA completion order.
// ---------------------------------------------------------------------------
__device__ __noinline__ void finalize_column(int b, int q0, float* out) {
    __shared__ long long    sred[THREADS_];
    __shared__ unsigned int s_f;

    long long acc = 0;
#pragma unroll
    for (int r = 0; r < RPT_; r++) {
        int gi = b * M_ + q0 + r * THREADS_;
        float d = dec_f32(~g_best[gi]);
        g_best[gi] = 0u;                       // re-arm for next replay
        acc += __float2ll_rn(d * SCALEF_);     // deterministic fixed-point
    }
    sred[threadIdx.x] = acc;
    __syncthreads();
#pragma unroll
    for (int off = THREADS_ / 2; off > 0; off >>= 1) {
        if (threadIdx.x < off) sred[threadIdx.x] += sred[threadIdx.x + off];
        __syncthreads();
    }
    if (threadIdx.x == 0) {
        atomicAdd(&g_isum, (unsigned long long)sred[0]);
        __threadfence();
        s_f = atomicAdd(&g_fticket, 1u);
    }
    __syncthreads();

    if (s_f == NCOLS_ - 1 && threadIdx.x == 0) {   // very last column-finisher
        __threadfence();
        long long tot = (long long)g_isum;
        out[0] = (float)((double)tot / SCALED_ / (double)(B_ * M_));
        g_isum = 0ull;                         // re-arm for next replay
        g_fticket = 0u;
    }
}

// ---------------------------------------------------------------------------
// Single kernel: fused refine + nearest-point minima (atomicMax of ~enc) +
// in-kernel deterministic reduction via non-blocking tickets.
// grid = (4,4,37) = 592 blocks: one co-resident wave at 4 CTAs/SM.
// ---------------------------------------------------------------------------
__global__ __launch_bounds__(THREADS_, 4)
void dist_kernel(const float* __restrict__ mesh, const float* __restrict__ pc,
                 float* __restrict__ out) {
    __shared__ ulonglong2 sa[PAIRS_];   // {x0,x1},{y0,y1}
    __shared__ ulonglong2 sb[PAIRS_];   // {z0,z1},{w0,w1}   w = |m|^2
    __shared__ unsigned int s_t;

    const int b     = blockIdx.x;
    const int chunk = blockIdx.y;
    const int s     = blockIdx.z;

    const int base = s * SLICE_;
    const int cnt  = (base + SLICE_ <= NMESH_) ? SLICE_ : (NMESH_ - base);  // even

    // --- Inline bilinear refine (align_corners, factor 3) for this slice ---
    const float* __restrict__ m0 = mesh + (b * 3 + 0) * H_ * W_;
    const float* __restrict__ m1 = mesh + (b * 3 + 1) * H_ * W_;
    const float* __restrict__ m2 = mesh + (b * 3 + 2) * H_ * W_;

    if (threadIdx.x < cnt) {
        int i = threadIdx.x;                 // SLICE_ <= THREADS_, one pass
        int idx = base + i;
        int r = idx / OW_;
        int c = idx - r * OW_;
        int y0 = r / FAC_; if (y0 > H_ - 2) y0 = H_ - 2;
        int x0 = c / FAC_; if (x0 > W_ - 2) x0 = W_ - 2;
        float wy = (float)r / (float)FAC_ - (float)y0;
        float wx = (float)c / (float)FAC_ - (float)x0;
        int o00 = y0 * W_ + x0, o01 = o00 + 1, o10 = o00 + W_, o11 = o10 + 1;

        float t0 = m0[o00] * (1.0f - wx) + m0[o01] * wx;
        float u0 = m0[o10] * (1.0f - wx) + m0[o11] * wx;
        float v0 = t0 * (1.0f - wy) + u0 * wy;

        float t1 = m1[o00] * (1.0f - wx) + m1[o01] * wx;
        float u1 = m1[o10] * (1.0f - wx) + m1[o11] * wx;
        float v1 = t1 * (1.0f - wy) + u1 * wy;

        float t2 = m2[o00] * (1.0f - wx) + m2[o01] * wx;
        float u2 = m2[o10] * (1.0f - wx) + m2[o11] * wx;
        float v2 = t2 * (1.0f - wy) + u2 * wy;

        float w = fmaf(v0, v0, fmaf(v1, v1, v2 * v2));

        int jp   = i >> 1;
        int lane = i & 1;
        float* fa = (float*)sa;
        float* fb = (float*)sb;
        fa[4 * jp + lane]     = v0;
        fa[4 * jp + 2 + lane] = v1;
        fb[4 * jp + lane]     = v2;
        fb[4 * jp + 2 + lane] = w;
    }
    __syncthreads();

    // --- Load this thread's pc points; duplicate coords into packed regs ---
    const float* __restrict__ px = pc + (b * 3 + 0) * M_;
    const float* __restrict__ py = pc + (b * 3 + 1) * M_;
    const float* __restrict__ pz = pc + (b * 3 + 2) * M_;

    const int q0 = chunk * (THREADS_ * RPT_) + threadIdx.x;   // pc point index

    unsigned long long ax2[RPT_], ay2[RPT_], az2[RPT_];
    float b0[RPT_], b1[RPT_];
#pragma unroll
    for (int r = 0; r < RPT_; r++) {
        int q = q0 + r * THREADS_;
        float x = px[q], y = py[q], z = pz[q];
        ax2[r] = pack2(-2.0f * x, -2.0f * x);
        ay2[r] = pack2(-2.0f * y, -2.0f * y);
        az2[r] = pack2(-2.0f * z, -2.0f * z);
        b0[r] = FLT_MAX;
        b1[r] = FLT_MAX;
    }

    // --- Hot loop over mesh PAIRS: one packed FMA chain = 2 mesh distances ---
    const int pairs = cnt >> 1;
#pragma unroll 2
    for (int jp = 0; jp < pairs; jp++) {
        ulonglong2 A  = sa[jp];   // broadcast LDS.128: {x0,x1},{y0,y1}
        ulonglong2 Bv = sb[jp];   // {z0,z1},{w0,w1}
#pragma unroll
        for (int r = 0; r < RPT_; r++) {
            df2 t;
            t.u = fma2(A.x, ax2[r], fma2(A.y, ay2[r], fma2(Bv.x, az2[r], Bv.y)));
            b0[r] = fminf(b0[r], t.f.x);
            b1[r] = fminf(b1[r], t.f.y);
        }
    }

    // --- Epilogue: per-point order-independent atomic min (exact) ---
#pragma unroll
    for (int r = 0; r < RPT_; r++) {
        int q = q0 + r * THREADS_;
        float x = px[q], y = py[q], z = pz[q];
        float pp = fmaf(x, x, fmaf(y, y, z * z));
        float d  = fminf(b0[r], b1[r]) + pp;
        atomicMax(&g_best[b * M_ + q], ~enc_f32(d));   // 0 == +inf sentinel
    }

    // --- Column ticket: last of 37 CTAs in this (b,chunk) column finalizes ---
    __threadfence();
    if (threadIdx.x == 0)
        s_t = atomicAdd(&g_colticket[b * CHUNKS_ + chunk], 1u);
    __syncthreads();

    if (s_t == SLICES_ - 1) {
        __threadfence();                       // acquire all writers' g_best
        if (threadIdx.x == 0)
            g_colticket[b * CHUNKS_ + chunk] = 0u;   // re-arm
        finalize_column(b, q0, out);
    }
}

// ---------------------------------------------------------------------------
extern "C" void kernel_launch(void* const* d_in, const int* in_sizes, int n_in,
                              void* d_out, int out_size) {
    const float* mesh = (const float*)d_in[0];
    const float* pc   = (const float*)d_in[1];
    float* out = (float*)d_out;

    dim3 grid(B_, CHUNKS_, SLICES_);
    dist_kernel<<<grid, THREADS_>>>(mesh, pc, out);
}